// round 6
// baseline (speedup 1.0000x reference)
#include <cuda_runtime.h>
#include <cstdint>

// LBFGS two-loop recursion, pair-split + lookahead version.
// grid = 128 independent CTAs = 64 batches x 2 halves of D (no clusters).
// Each CTA streams its 32KB half-rows through a 6-stage TMA ring.
// Cross-CTA dot reduction: each CTA computes LOCAL partial dots using a
// one-step-stale q (lag identity  s_t.q(t) = s_t.q(t-1) - a_{t-1} s_t.y_{t-1}),
// publishes partials to L2 scratch (release/acquire + per-launch epoch), and
// combines the PREVIOUS step's partials one iteration later -- the exchange
// latency hides under the next step's vector work. Both halves replicate the
// scalar recursion from identical summed partials (commutative add -> bit-
// identical coefficients).

#define MM 32
#define BB 64
#define DD 8192
#define HD (DD / 2)              // 4096 floats per CTA
#define NT 512
#define NW (NT / 32)             // 16 warps
#define STAGES 6
#define HROW_BYTES (HD * 4)      // 16 KB
#define STAGE_BYTES (2 * HROW_BYTES)   // 32 KB (s half + y half)
#define SMEM_SMALL 1024
#define SMEM_TOTAL (SMEM_SMALL + STAGES * STAGE_BYTES)  // 197632

// small smem region offsets
#define OFF_MBAR   0     // 6 x 8B
#define OFF_RED    64    // 3 x 32 floats = 384B
#define OFF_OWN    448   // own totals, 2 parity x 16B
#define OFF_COEFF  480   // broadcast coefficient
#define OFF_GS     484   // gscale
#define OFF_RARR   512   // 32 floats (thread0 only)
#define OFF_AARR   640   // 32 floats (thread0 only)

// L2 exchange scratch (static device globals -- no allocation)
__device__ float    g_part[2 * MM][BB][2][4];
__device__ unsigned g_flag[2 * MM][BB][2];
__device__ unsigned g_epoch;

__global__ void epoch_bump_kernel() { g_epoch = g_epoch + 1u; }

__device__ __forceinline__ uint32_t smem_u32(const void* p) {
    return (uint32_t)__cvta_generic_to_shared(p);
}
__device__ __forceinline__ void mbar_init(uint32_t mbar, uint32_t count) {
    asm volatile("mbarrier.init.shared::cta.b64 [%0], %1;" :: "r"(mbar), "r"(count));
}
__device__ __forceinline__ void mbar_expect_tx(uint32_t mbar, uint32_t bytes) {
    asm volatile("mbarrier.arrive.expect_tx.shared::cta.b64 _, [%0], %1;"
                 :: "r"(mbar), "r"(bytes) : "memory");
}
__device__ __forceinline__ void bulk_g2s(uint32_t dst, const void* src,
                                         uint32_t bytes, uint32_t mbar) {
    asm volatile(
        "cp.async.bulk.shared::cluster.global.mbarrier::complete_tx::bytes "
        "[%0], [%1], %2, [%3];"
        :: "r"(dst), "l"(src), "r"(bytes), "r"(mbar) : "memory");
}
__device__ __forceinline__ void mbar_wait(uint32_t mbar, uint32_t parity) {
    uint32_t done;
    asm volatile(
        "{\n\t.reg .pred p;\n\t"
        "mbarrier.try_wait.parity.acquire.cta.shared::cta.b64 p, [%1], %2;\n\t"
        "selp.b32 %0, 1, 0, p;\n\t}"
        : "=r"(done) : "r"(mbar), "r"(parity) : "memory");
    if (!done) {
        asm volatile(
            "{\n\t.reg .pred P1;\n\t"
            "WL_%=:\n\t"
            "mbarrier.try_wait.parity.acquire.cta.shared::cta.b64 P1, [%0], %1, 0x989680;\n\t"
            "@P1 bra.uni WD_%=;\n\t"
            "bra.uni WL_%=;\n\t"
            "WD_%=:\n\t}"
            :: "r"(mbar), "r"(parity) : "memory");
    }
}

__device__ __forceinline__ float dot4(float4 a, float4 b) {
    return a.x * b.x + a.y * b.y + a.z * b.z + a.w * b.w;
}
__device__ __forceinline__ void fma4(float4& q, float c, float4 v) {
    q.x += c * v.x; q.y += c * v.y; q.z += c * v.z; q.w += c * v.w;
}
__device__ __forceinline__ int seq_row(int t) {   // palindromic order
    return (t < MM) ? (MM - 1 - t) : (t - MM);
}

// publish (lane0 of warp0): partial record then release-flag
__device__ __forceinline__ void publish(int t, int b, int half,
                                        float x0, float x1, float x2,
                                        unsigned epoch) {
    float4 rec; rec.x = x0; rec.y = x1; rec.z = x2; rec.w = 0.0f;
    *(float4*)&g_part[t][b][half][0] = rec;
    asm volatile("st.release.gpu.global.u32 [%0], %1;"
                 :: "l"(&g_flag[t][b][half]), "r"(epoch) : "memory");
}

// poll peer record (thread0 only)
__device__ __forceinline__ float4 poll_peer(int t, int b, int half_peer,
                                            unsigned epoch) {
    unsigned v;
    unsigned* fl = &g_flag[t][b][half_peer];
    do {
        asm volatile("ld.acquire.gpu.global.u32 %0, [%1];"
                     : "=r"(v) : "l"(fl) : "memory");
    } while (v != epoch);
    return *(const float4*)&g_part[t][b][half_peer][0];
}

__global__ __launch_bounds__(NT, 1)
void lbfgs_pair_kernel(const float* __restrict__ S,
                       const float* __restrict__ Y,
                       const float* __restrict__ FRC,
                       float* __restrict__ OUT) {
    extern __shared__ __align__(1024) char smem[];
    float* red    = (float*)(smem + OFF_RED);
    float* own    = (float*)(smem + OFF_OWN);
    float* coeffp = (float*)(smem + OFF_COEFF);
    float* gsv    = (float*)(smem + OFF_GS);
    float* r_arr  = (float*)(smem + OFF_RARR);
    float* a_arr  = (float*)(smem + OFF_AARR);
    const uint32_t mbar0  = smem_u32(smem + OFF_MBAR);
    const uint32_t stage0 = smem_u32(smem + SMEM_SMALL);

    const int b    = blockIdx.x >> 1;
    const int half = blockIdx.x & 1;
    const int tid  = threadIdx.x;
    const int lane = tid & 31;
    const int wid  = tid >> 5;

    const unsigned epoch = g_epoch;

    if (tid == 0) {
#pragma unroll
        for (int s = 0; s < STAGES; ++s) mbar_init(mbar0 + s * 8, 1);
    }
    asm volatile("fence.proxy.async.shared::cta;" ::: "memory");
    __syncthreads();

    auto issue = [&](int stage, int t) {
        const int row = seq_row(t);
        const size_t off = ((size_t)row * BB + b) * DD + (size_t)half * HD;
        const uint32_t m   = mbar0 + stage * 8;
        const uint32_t dst = stage0 + stage * STAGE_BYTES;
        mbar_expect_tx(m, STAGE_BYTES);
        bulk_g2s(dst,              S + off, HROW_BYTES, m);
        bulk_g2s(dst + HROW_BYTES, Y + off, HROW_BYTES, m);
    };

    if (tid == 0) {
#pragma unroll
        for (int s = 0; s < STAGES; ++s) issue(s, s);
    }

    // q = -frc (half-D slice, 8 floats/thread)
    float4 q0, q1;
    {
        const float4* F4 = (const float4*)(FRC + (size_t)b * DD + (size_t)half * HD);
        float4 a = F4[tid], c = F4[tid + NT];
        q0.x = -a.x; q0.y = -a.y; q0.z = -a.z; q0.w = -a.w;
        q1.x = -c.x; q1.y = -c.y; q1.z = -c.z; q1.w = -c.w;
    }

    float4 keep0 = make_float4(0.f, 0.f, 0.f, 0.f);
    float4 keep1 = keep0;
    float a_prev = 0.0f, c_prev = 0.0f;   // thread0 scalar state

#pragma unroll 1
    for (int t = 0; t < 2 * MM; ++t) {
        const int stage = t % STAGES;
        const uint32_t parity = (uint32_t)(t / STAGES) & 1u;

        mbar_wait(mbar0 + stage * 8, parity);

        const float4* sS = (const float4*)(smem + SMEM_SMALL + stage * STAGE_BYTES);
        const float4* sY = (const float4*)(smem + SMEM_SMALL + stage * STAGE_BYTES + HROW_BYTES);
        float4 sc0 = sS[tid], sc1 = sS[tid + NT];
        float4 yc0 = sY[tid], yc1 = sY[tid + NT];

        if (t == MM) {
            // flush backward: combine step MM-1 (a for row i=0), apply, scale
            if (tid == 0) {
                float4 P = poll_peer(MM - 1, b, half ^ 1, epoch);
                const float* ow = own + ((MM - 1) & 1) * 4;
                const float TE = ow[0] + P.x, TF = ow[1] + P.y, TD = ow[2] + P.z;
                const float a = (TE - a_prev * TF) / TD;
                r_arr[0] = 1.0f / TD; a_arr[0] = a;
                coeffp[0] = -a;
                c_prev = 0.0f;
            }
            __syncthreads();
            const float cf = coeffp[0];
            const float g  = gsv[0];
            fma4(q0, cf, keep0); fma4(q1, cf, keep1);
            q0.x *= g; q0.y *= g; q0.z *= g; q0.w *= g;
            q1.x *= g; q1.y *= g; q1.z *= g; q1.w *= g;
        }

        const bool bwd = (t < MM);

        // ---- local partial dots (lag form: q is stale by one coefficient) ----
        float v0, v1, v2;
        if (bwd) {
            v0 = dot4(sc0, q0) + dot4(sc1, q1);                 // e = s_t . q
            v2 = dot4(sc0, yc0) + dot4(sc1, yc1);               // d = s_t . y_t
            v1 = (t == 0) ? (dot4(yc0, yc0) + dot4(yc1, yc1))   // yy (for g)
                          : (dot4(sc0, keep0) + dot4(sc1, keep1)); // f = s_t . y_{t-1}
        } else {
            v0 = dot4(yc0, q0) + dot4(yc1, q1);                 // e = y_t . q
            v1 = (t > MM) ? (dot4(yc0, keep0) + dot4(yc1, keep1)) : 0.0f; // f = y_t . s_{t-1}
            v2 = 0.0f;
        }

#pragma unroll
        for (int off = 16; off > 0; off >>= 1) {
            v0 += __shfl_xor_sync(0xffffffffu, v0, off);
            v1 += __shfl_xor_sync(0xffffffffu, v1, off);
            if (bwd) v2 += __shfl_xor_sync(0xffffffffu, v2, off);
        }
        if (lane == 0) {
            red[wid] = v0; red[32 + wid] = v1;
            if (bwd) red[64 + wid] = v2;
        }
        __syncthreads();   // bar1: stage consumed, partials posted

        if (tid == 32 && t + STAGES < 2 * MM) issue(stage, t + STAGES);

        if (wid == 0) {
            float x0 = (lane < NW) ? red[lane] : 0.0f;
            float x1 = (lane < NW) ? red[32 + lane] : 0.0f;
            float x2 = (bwd && lane < NW) ? red[64 + lane] : 0.0f;
#pragma unroll
            for (int off = 8; off > 0; off >>= 1) {
                x0 += __shfl_xor_sync(0xffffffffu, x0, off);
                x1 += __shfl_xor_sync(0xffffffffu, x1, off);
                x2 += __shfl_xor_sync(0xffffffffu, x2, off);
            }
            if (lane == 0) {
                float* ow = own + (t & 1) * 4;
                ow[0] = x0; ow[1] = x1; ow[2] = x2;
                publish(t, b, half, x0, x1, x2, epoch);

                if (t == 0 || t == MM) {
                    coeffp[0] = 0.0f;
                } else {
                    // combine step t-1 (peer partials are ~1 step old: poll hits fast)
                    float4 P = poll_peer(t - 1, b, half ^ 1, epoch);
                    const float* po = own + ((t - 1) & 1) * 4;
                    const float TE = po[0] + P.x, TF = po[1] + P.y, TD = po[2] + P.z;
                    if (t - 1 < MM) {
                        const int i = MM - 1 - (t - 1);
                        const float F = (t - 1 == 0) ? 0.0f : TF;
                        const float a = (TE - a_prev * F) / TD;
                        r_arr[i] = 1.0f / TD; a_arr[i] = a;
                        a_prev = a;
                        coeffp[0] = -a;
                        if (t - 1 == 0) gsv[0] = TD / TF;   // TF slot held y.y at t=0
                    } else {
                        const int i = (t - 1) - MM;
                        const float bb_ = r_arr[i] * (TE + c_prev * TF);
                        const float c   = a_arr[i] - bb_;
                        c_prev = c;
                        coeffp[0] = c;
                    }
                }
            }
        }
        __syncthreads();   // bar2: coefficient broadcast

        const float cf = coeffp[0];
        fma4(q0, cf, keep0); fma4(q1, cf, keep1);   // deferred axpy of step t-1

        // keep operand for next step's f-dot and deferred axpy
        if (bwd) { keep0 = yc0; keep1 = yc1; }
        else     { keep0 = sc0; keep1 = sc1; }
    }

    // final flush: combine step 2MM-1 (c for row i=31), apply, write out
    if (tid == 0) {
        float4 P = poll_peer(2 * MM - 1, b, half ^ 1, epoch);
        const float* po = own + ((2 * MM - 1) & 1) * 4;
        const float TE = po[0] + P.x, TF = po[1] + P.y;
        const int i = MM - 1;
        const float bb_ = r_arr[i] * (TE + c_prev * TF);
        coeffp[0] = a_arr[i] - bb_;
    }
    __syncthreads();
    const float cf = coeffp[0];
    fma4(q0, cf, keep0); fma4(q1, cf, keep1);

    float4* O4 = (float4*)(OUT + (size_t)b * DD + (size_t)half * HD);
    float4 o0, o1;
    o0.x = -q0.x; o0.y = -q0.y; o0.z = -q0.z; o0.w = -q0.w;
    o1.x = -q1.x; o1.y = -q1.y; o1.z = -q1.z; o1.w = -q1.w;
    O4[tid]      = o0;
    O4[tid + NT] = o1;
}

extern "C" void kernel_launch(void* const* d_in, const int* in_sizes, int n_in,
                              void* d_out, int out_size) {
    const float* S   = (const float*)d_in[0];  // (M, B, D) fp32
    const float* Y   = (const float*)d_in[1];  // (M, B, D) fp32
    const float* FRC = (const float*)d_in[2];  // (B, D)    fp32
    float* OUT = (float*)d_out;                // (B, D)    fp32

    static bool attr_set = false;
    if (!attr_set) {
        cudaFuncSetAttribute(lbfgs_pair_kernel,
                             cudaFuncAttributeMaxDynamicSharedMemorySize,
                             SMEM_TOTAL);
        attr_set = true;
    }
    // per-launch epoch so exchange flags from prior replays can't satisfy polls
    epoch_bump_kernel<<<1, 1>>>();
    lbfgs_pair_kernel<<<2 * BB, NT, SMEM_TOTAL>>>(S, Y, FRC, OUT);
}

// round 7
// speedup vs baseline: 1.2484x; 1.2484x over previous
#include <cuda_runtime.h>
#include <cstdint>

// LBFGS two-loop recursion, Gram-matrix reformulation.
// All 64 scalar coefficients derive from small Gram data:
//   E[i][j] = s_i.y_j   (32x32 per batch)     w[i] = s_i.frc
//   a_i = (-w_i - sum_{j>i} a_j E[i][j]) / E[i][i]        (K2a)
//   qb  = -frc - sum_j a_j y_j ;  v[i] = y_i.qb           (K3)
//   c_i = a_i - r_i (g v_i + sum_{j<i} c_j E[j][i])       (K2b)
//   out = -(g qb + sum_i c_i s_i)                          (K5)
// No 64-deep serial chain over the 2MB carry: every heavy kernel is
// embarrassingly parallel streaming at full chip width.

#define MM 32
#define BB 64
#define DD 8192

#define CH1 256
#define NCH1 (DD / CH1)          // 32
#define ST1 260                  // padded smem row stride (floats)
#define K1_SMEM ((2 * 32 * ST1 + CH1) * 4)   // 67584 B

#define CH3 512
#define NCH3 (DD / CH3)          // 16

typedef unsigned long long u64;

// ---------------- device scratch (static: no allocation) ----------------
__device__ float gE[BB * MM * MM];   // s_i . y_j
__device__ float gw[BB * MM];        // s_i . frc
__device__ float gv[BB * MM];        // y_i . qb
__device__ float gyy[BB];            // y_31 . y_31
__device__ float ga[BB * MM];
__device__ float gr[BB * MM];
__device__ float gc[BB * MM];
__device__ float gg[BB];
__device__ float gqb[BB * DD];

// ---------------- f32x2 helpers ----------------
__device__ __forceinline__ u64 pk2(float a, float b) {
    u64 r; asm("mov.b64 %0, {%1,%2};" : "=l"(r) : "f"(a), "f"(b)); return r;
}
__device__ __forceinline__ float2 upk2(u64 v) {
    float2 f; asm("mov.b64 {%0,%1}, %2;" : "=f"(f.x), "=f"(f.y) : "l"(v)); return f;
}
__device__ __forceinline__ u64 fma2(u64 a, u64 b, u64 c) {
    u64 d; asm("fma.rn.f32x2 %0, %1, %2, %3;" : "=l"(d) : "l"(a), "l"(b), "l"(c)); return d;
}
__device__ __forceinline__ float dot4(float4 a, float4 b) {
    return a.x * b.x + a.y * b.y + a.z * b.z + a.w * b.w;
}

// ---------------- K0: zero accumulators ----------------
__global__ void k0_zero() {
    const int b = blockIdx.x;
    const int t = threadIdx.x;
    gE[b * (MM * MM) + t] = 0.0f;
    if (t < MM) { gw[b * MM + t] = 0.0f; gv[b * MM + t] = 0.0f; }
    if (t == 0) gyy[b] = 0.0f;
}

// ---------------- K1: Gram (E full, w, yy_last) ----------------
__global__ __launch_bounds__(256, 2)
void k1_gram(const float* __restrict__ S, const float* __restrict__ Y,
             const float* __restrict__ FRC) {
    extern __shared__ __align__(16) float smem[];
    float* sS = smem;                 // 32 x ST1
    float* sY = smem + 32 * ST1;      // 32 x ST1
    float* sF = smem + 64 * ST1;      // CH1

    const int b  = blockIdx.x >> 5;
    const int ch = blockIdx.x & 31;
    const int tid = threadIdx.x;

    // load S,Y 32x256 tiles (coalesced float4) into padded smem
#pragma unroll
    for (int r = 0; r < 8; ++r) {
        const int idx = r * 256 + tid;
        const int row = idx >> 6;          // 64 float4 per row
        const int c4  = idx & 63;
        const size_t g = ((size_t)row * BB + b) * DD + (size_t)ch * CH1 + c4 * 4;
        *(float4*)&sS[row * ST1 + c4 * 4] = *(const float4*)(S + g);
        *(float4*)&sY[row * ST1 + c4 * 4] = *(const float4*)(Y + g);
    }
    if (tid < 64) {
        *(float4*)&sF[tid * 4] =
            *(const float4*)(FRC + (size_t)b * DD + (size_t)ch * CH1 + tid * 4);
    }
    __syncthreads();

    // 4x4 register tile per thread: rows i0+8k, cols j0+8l, d-quarter dq
    const int tile = tid & 63;
    const int dq   = tid >> 6;
    const int i0   = tile >> 3;          // 0..7
    const int j0   = tile & 7;           // 0..7
    const int dbase = dq * 64;

    u64 acc[16];
#pragma unroll
    for (int n = 0; n < 16; ++n) acc[n] = 0ull;

#pragma unroll
    for (int d4 = 0; d4 < 16; ++d4) {
        const int c = dbase + d4 * 4;
        ulonglong2 su[4], yu[4];
#pragma unroll
        for (int k = 0; k < 4; ++k)
            su[k] = *(const ulonglong2*)&sS[(i0 + 8 * k) * ST1 + c];
#pragma unroll
        for (int l = 0; l < 4; ++l)
            yu[l] = *(const ulonglong2*)&sY[(j0 + 8 * l) * ST1 + c];
#pragma unroll
        for (int k = 0; k < 4; ++k)
#pragma unroll
            for (int l = 0; l < 4; ++l) {
                acc[k * 4 + l] = fma2(su[k].x, yu[l].x, acc[k * 4 + l]);
                acc[k * 4 + l] = fma2(su[k].y, yu[l].y, acc[k * 4 + l]);
            }
    }

#pragma unroll
    for (int k = 0; k < 4; ++k)
#pragma unroll
        for (int l = 0; l < 4; ++l) {
            float2 p = upk2(acc[k * 4 + l]);
            atomicAdd(&gE[b * (MM * MM) + (i0 + 8 * k) * MM + (j0 + 8 * l)],
                      p.x + p.y);
        }

    // w[i] = s_i . frc  (warp w handles rows w, w+8, w+16, w+24)
    const int wrp  = tid >> 5;
    const int lane = tid & 31;
#pragma unroll
    for (int m = 0; m < 4; ++m) {
        const int i = wrp + 8 * m;
        float4 a0 = *(const float4*)&sS[i * ST1 + lane * 8];
        float4 a1 = *(const float4*)&sS[i * ST1 + lane * 8 + 4];
        float4 f0 = *(const float4*)&sF[lane * 8];
        float4 f1 = *(const float4*)&sF[lane * 8 + 4];
        float t = dot4(a0, f0) + dot4(a1, f1);
#pragma unroll
        for (int off = 16; off > 0; off >>= 1)
            t += __shfl_xor_sync(0xffffffffu, t, off);
        if (lane == 0) atomicAdd(&gw[b * MM + i], t);
        if (i == MM - 1) {
            float4 y0 = *(const float4*)&sY[i * ST1 + lane * 8];
            float4 y1 = *(const float4*)&sY[i * ST1 + lane * 8 + 4];
            float yy = dot4(y0, y0) + dot4(y1, y1);
#pragma unroll
            for (int off = 16; off > 0; off >>= 1)
                yy += __shfl_xor_sync(0xffffffffu, yy, off);
            if (lane == 0) atomicAdd(&gyy[b], yy);
        }
    }
}

// ---------------- K2a: backward solve (a, r, g) — one warp per batch ----
__global__ void k2a_solve(void) {
    const int b = blockIdx.x;
    const int j = threadIdx.x;   // 32 threads

    float e[MM];
#pragma unroll
    for (int i = 0; i < MM; ++i) e[i] = gE[b * (MM * MM) + i * MM + j];  // E[i][j]
    const float w_own = gw[MM * b + j];

    float a_own = 0.0f, r_own = 0.0f, e3131 = 1.0f;
#pragma unroll
    for (int ii = 0; ii < MM; ++ii) {
        const int i = MM - 1 - ii;
        float contrib = (j > i) ? a_own * e[i] : 0.0f;
#pragma unroll
        for (int off = 16; off > 0; off >>= 1)
            contrib += __shfl_xor_sync(0xffffffffu, contrib, off);
        const float ediag = __shfl_sync(0xffffffffu, e[i], i);
        const float wi    = __shfl_sync(0xffffffffu, w_own, i);
        const float ai    = (-wi - contrib) / ediag;
        if (j == i) { a_own = ai; r_own = 1.0f / ediag; }
        if (ii == 0) e3131 = ediag;
    }
    ga[b * MM + j] = a_own;
    gr[b * MM + j] = r_own;
    if (j == 0) gg[b] = e3131 / gyy[b];
}

// ---------------- K3: qb = -frc - sum a_j y_j ;  v[i] = y_i . qb --------
__global__ __launch_bounds__(256)
void k3_qb(const float* __restrict__ Y, const float* __restrict__ FRC) {
    __shared__ float sa[MM];
    __shared__ float sqb[CH3];

    const int b  = blockIdx.x >> 4;
    const int ch = blockIdx.x & 15;
    const int tid = threadIdx.x;

    if (tid < MM) sa[tid] = ga[b * MM + tid];
    __syncthreads();

    const size_t d0 = (size_t)ch * CH3 + 2 * tid;
    float2 f = *(const float2*)(FRC + (size_t)b * DD + d0);
    u64 acc = pk2(-f.x, -f.y);
#pragma unroll
    for (int j = 0; j < MM; ++j) {
        u64 yj = *(const u64*)(Y + ((size_t)j * BB + b) * DD + d0);
        const float na = -sa[j];
        acc = fma2(pk2(na, na), yj, acc);
    }
    float2 qb = upk2(acc);
    *(float2*)(gqb + (size_t)b * DD + d0) = qb;
    *(float2*)&sqb[2 * tid] = qb;
    __syncthreads();

    // v: warp w handles rows w, w+8, w+16, w+24 (y rows re-read: L1-hot)
    const int wrp  = tid >> 5;
    const int lane = tid & 31;
#pragma unroll
    for (int m = 0; m < 4; ++m) {
        const int i = wrp + 8 * m;
        const float4* yrow =
            (const float4*)(Y + ((size_t)i * BB + b) * DD + (size_t)ch * CH3);
        float t = 0.0f;
#pragma unroll
        for (int p = 0; p < 4; ++p) {
            float4 yv = yrow[lane + 32 * p];
            float4 qv = *(const float4*)&sqb[(lane + 32 * p) * 4];
            t += dot4(yv, qv);
        }
#pragma unroll
        for (int off = 16; off > 0; off >>= 1)
            t += __shfl_xor_sync(0xffffffffu, t, off);
        if (lane == 0) atomicAdd(&gv[b * MM + i], t);
    }
}

// ---------------- K2b: forward solve (c) — one warp per batch -----------
__global__ void k2b_solve(void) {
    const int b = blockIdx.x;
    const int j = threadIdx.x;

    float e[MM];   // row j of E: E[j][i]
    {
        const float4* row4 = (const float4*)(gE + b * (MM * MM) + j * MM);
#pragma unroll
        for (int q = 0; q < 8; ++q) {
            float4 v = row4[q];
            e[q * 4 + 0] = v.x; e[q * 4 + 1] = v.y;
            e[q * 4 + 2] = v.z; e[q * 4 + 3] = v.w;
        }
    }
    const float r_own = gr[b * MM + j];
    const float a_own = ga[b * MM + j];
    const float v_own = gv[b * MM + j];
    const float g = gg[b];
    float c_own = 0.0f;

#pragma unroll
    for (int i = 0; i < MM; ++i) {
        float contrib = (j < i) ? c_own * e[i] : 0.0f;
#pragma unroll
        for (int off = 16; off > 0; off >>= 1)
            contrib += __shfl_xor_sync(0xffffffffu, contrib, off);
        const float ri = __shfl_sync(0xffffffffu, r_own, i);
        const float ai = __shfl_sync(0xffffffffu, a_own, i);
        const float vi = __shfl_sync(0xffffffffu, v_own, i);
        const float ci = ai - ri * (g * vi + contrib);
        if (j == i) c_own = ci;
    }
    gc[b * MM + j] = c_own;
}

// ---------------- K5: out = -(g qb + sum c_i s_i) ------------------------
__global__ __launch_bounds__(256)
void k5_out(const float* __restrict__ S, float* __restrict__ OUT) {
    __shared__ float sc[MM];
    __shared__ float sgv[1];

    const int b  = blockIdx.x >> 4;
    const int ch = blockIdx.x & 15;
    const int tid = threadIdx.x;

    if (tid < MM) sc[tid] = gc[b * MM + tid];
    if (tid == MM) sgv[0] = gg[b];
    __syncthreads();

    const size_t d0 = (size_t)ch * CH3 + 2 * tid;
    const float g = sgv[0];
    float2 qb = *(const float2*)(gqb + (size_t)b * DD + d0);
    u64 acc = pk2(-g * qb.x, -g * qb.y);
#pragma unroll
    for (int i = 0; i < MM; ++i) {
        u64 si = *(const u64*)(S + ((size_t)i * BB + b) * DD + d0);
        const float nc = -sc[i];
        acc = fma2(pk2(nc, nc), si, acc);
    }
    *(float2*)(OUT + (size_t)b * DD + d0) = upk2(acc);
}

// ---------------- launch ----------------
extern "C" void kernel_launch(void* const* d_in, const int* in_sizes, int n_in,
                              void* d_out, int out_size) {
    const float* S   = (const float*)d_in[0];  // (M, B, D)
    const float* Y   = (const float*)d_in[1];  // (M, B, D)
    const float* FRC = (const float*)d_in[2];  // (B, D)
    float* OUT = (float*)d_out;                // (B, D)

    static bool attr_set = false;
    if (!attr_set) {
        cudaFuncSetAttribute(k1_gram,
                             cudaFuncAttributeMaxDynamicSharedMemorySize,
                             K1_SMEM);
        attr_set = true;
    }

    k0_zero<<<BB, MM * MM>>>();
    k1_gram<<<BB * NCH1, 256, K1_SMEM>>>(S, Y, FRC);
    k2a_solve<<<BB, 32>>>();
    k3_qb<<<BB * NCH3, 256>>>(Y, FRC);
    k2b_solve<<<BB, 32>>>();
    k5_out<<<BB * NCH3, 256>>>(S, OUT);
}